// round 1
// baseline (speedup 1.0000x reference)
#include <cuda_runtime.h>
#include <math.h>

#define B_  16384
#define S_  256
#define E_  128
#define H_  128
#define N_  34

// output layout (floats): rep_vec [B,384] | log_task_prob [B,34] | latent_target [B,128] | latent_vec [B,128]
#define REP_OFF  0
#define LP_OFF   (B_*(S_+E_))                // 6291456
#define LT_OFF   (LP_OFF + B_*N_)            // 6848512
#define LV_OFF   (LT_OFF + B_*E_)            // 8945664

__device__ float g_cos[(size_t)B_*N_];   // cos_sim scratch
__device__ float g_lat[(size_t)B_*E_];   // latent_vec accumulator

// smem layout (floats)
#define ACT_STRIDE 130
#define ACT_FLOATS (128*ACT_STRIDE)   // 16640
#define AS_FLOATS  (128*33)           // 4224
#define BS_FLOATS  (32*128)           // 4096
#define SMEM_FLOATS (ACT_FLOATS + AS_FLOATS + BS_FLOATS + 3*128)
#define SMEM_BYTES  (SMEM_FLOATS * sizeof(float))

__global__ void zero_lat_kernel() {
    int idx = blockIdx.x * blockDim.x + threadIdx.x;   // grid 2048 x 256 -> 524288 = B_*E_/4
    float4 z = make_float4(0.f, 0.f, 0.f, 0.f);
    reinterpret_cast<float4*>(g_lat)[idx] = z;
}

// GEMM stage with A = Act (smem, [128][ACT_STRIDE]) and B = Wn ([K,128] row-major in gmem)
__device__ __forceinline__ void gemm_stage(float acc[8][8], const float* __restrict__ Wn,
                                           const float* Act, float* Bs,
                                           int tid, int tx, int ty, int K)
{
    for (int k0 = 0; k0 < K; k0 += 32) {
        __syncthreads();
        #pragma unroll
        for (int idx = tid; idx < 1024; idx += 256) {
            int k = idx >> 5, c = (idx & 31) << 2;
            *(float4*)(Bs + k*128 + c) = *(const float4*)(Wn + (size_t)(k0+k)*128 + c);
        }
        __syncthreads();
        #pragma unroll
        for (int k = 0; k < 32; k++) {
            float a[8];
            #pragma unroll
            for (int i = 0; i < 8; i++) a[i] = Act[(ty*8+i)*ACT_STRIDE + k0 + k];
            float4 u = *(const float4*)(Bs + k*128 + tx*8);
            float4 v = *(const float4*)(Bs + k*128 + tx*8 + 4);
            float bb[8] = {u.x,u.y,u.z,u.w,v.x,v.y,v.z,v.w};
            #pragma unroll
            for (int i = 0; i < 8; i++)
                #pragma unroll
                for (int j = 0; j < 8; j++) acc[i][j] = fmaf(a[i], bb[j], acc[i][j]);
        }
    }
}

__global__ __launch_bounds__(256, 2) void enc_main(
    const float* __restrict__ state, const int* __restrict__ task_id,
    const float* __restrict__ prior,
    const float* __restrict__ W1, const float* __restrict__ b1,
    const float* __restrict__ W2, const float* __restrict__ b2,
    const float* __restrict__ W3, const float* __restrict__ b3,
    const float* __restrict__ lang, float* __restrict__ out_lt)
{
    extern __shared__ float sm[];
    float* Act  = sm;
    float* As   = sm + ACT_FLOATS;
    float* Bs   = As + AS_FLOATS;
    float* pw   = Bs + BS_FLOATS;   // p(prior)_n * inv_norm_q per row
    float* invq = pw + 128;
    int*   trow = (int*)(invq + 128);

    const int n   = blockIdx.x;
    const int b0  = blockIdx.y * 128;
    const int tid = threadIdx.x;
    const int tx  = tid & 15, ty = tid >> 4;

    float acc[8][8];
    #pragma unroll
    for (int i = 0; i < 8; i++)
        #pragma unroll
        for (int j = 0; j < 8; j++) acc[i][j] = 0.f;

    // ---------- stage 1: state[128,256] @ W1[n] -> relu -> Act ----------
    const float* W1n = W1 + (size_t)n * S_ * H_;
    for (int k0 = 0; k0 < S_; k0 += 32) {
        __syncthreads();
        #pragma unroll
        for (int idx = tid; idx < 1024; idx += 256) {
            int row = idx >> 3, p = (idx & 7) << 2;
            float4 v = *(const float4*)(state + (size_t)(b0+row)*S_ + k0 + p);
            float* d = As + row*33 + p;
            d[0]=v.x; d[1]=v.y; d[2]=v.z; d[3]=v.w;
        }
        #pragma unroll
        for (int idx = tid; idx < 1024; idx += 256) {
            int k = idx >> 5, c = (idx & 31) << 2;
            *(float4*)(Bs + k*128 + c) = *(const float4*)(W1n + (size_t)(k0+k)*128 + c);
        }
        __syncthreads();
        #pragma unroll
        for (int k = 0; k < 32; k++) {
            float a[8];
            #pragma unroll
            for (int i = 0; i < 8; i++) a[i] = As[(ty*8+i)*33 + k];
            float4 u = *(const float4*)(Bs + k*128 + tx*8);
            float4 v = *(const float4*)(Bs + k*128 + tx*8 + 4);
            float bb[8] = {u.x,u.y,u.z,u.w,v.x,v.y,v.z,v.w};
            #pragma unroll
            for (int i = 0; i < 8; i++)
                #pragma unroll
                for (int j = 0; j < 8; j++) acc[i][j] = fmaf(a[i], bb[j], acc[i][j]);
        }
    }
    {
        const float* bp = b1 + n*H_;
        float4 u = *(const float4*)(bp + tx*8);
        float4 v = *(const float4*)(bp + tx*8 + 4);
        float bb[8] = {u.x,u.y,u.z,u.w,v.x,v.y,v.z,v.w};
        __syncthreads();
        #pragma unroll
        for (int i = 0; i < 8; i++)
            #pragma unroll
            for (int j = 0; j < 8; j++) {
                Act[(ty*8+i)*ACT_STRIDE + tx*8 + j] = fmaxf(acc[i][j] + bb[j], 0.f);
                acc[i][j] = 0.f;
            }
    }

    // ---------- stage 2: Act @ W2[n] -> relu -> Act ----------
    gemm_stage(acc, W2 + (size_t)n*H_*H_, Act, Bs, tid, tx, ty, H_);
    {
        const float* bp = b2 + n*H_;
        float4 u = *(const float4*)(bp + tx*8);
        float4 v = *(const float4*)(bp + tx*8 + 4);
        float bb[8] = {u.x,u.y,u.z,u.w,v.x,v.y,v.z,v.w};
        __syncthreads();
        #pragma unroll
        for (int i = 0; i < 8; i++)
            #pragma unroll
            for (int j = 0; j < 8; j++) {
                Act[(ty*8+i)*ACT_STRIDE + tx*8 + j] = fmaxf(acc[i][j] + bb[j], 0.f);
                acc[i][j] = 0.f;
            }
    }

    // ---------- stage 3: Act @ W3[n] + b3 -> q (raw) -> Act ----------
    gemm_stage(acc, W3 + (size_t)n*H_*E_, Act, Bs, tid, tx, ty, H_);
    {
        const float* bp = b3 + n*E_;
        float4 u = *(const float4*)(bp + tx*8);
        float4 v = *(const float4*)(bp + tx*8 + 4);
        float bb[8] = {u.x,u.y,u.z,u.w,v.x,v.y,v.z,v.w};
        __syncthreads();
        #pragma unroll
        for (int i = 0; i < 8; i++)
            #pragma unroll
            for (int j = 0; j < 8; j++)
                Act[(ty*8+i)*ACT_STRIDE + tx*8 + j] = acc[i][j] + bb[j];
    }
    __syncthreads();

    // ---------- per-row epilogue ----------
    if (tid < 128) {
        int r = tid;
        const float* qr = Act + r*ACT_STRIDE;
        int t = task_id[b0 + r];
        const float* lr = lang + (size_t)t * E_;
        float nq = 0.f, dot = 0.f, nl = 0.f;
        #pragma unroll 8
        for (int e = 0; e < E_; e++) {
            float q = qr[e];
            float L = lr[e];
            nq  = fmaf(q, q, nq);
            dot = fmaf(q, L, dot);
            nl  = fmaf(L, L, nl);
        }
        float iq = rsqrtf(nq);
        float il = 1.f / fmaxf(sqrtf(nl), 1e-8f);
        g_cos[(size_t)(b0+r)*N_ + n] = dot * iq * il;

        const float* pr = prior + (size_t)(b0+r)*N_;
        float m = -INFINITY;
        for (int nn = 0; nn < N_; nn++) m = fmaxf(m, pr[nn]);
        float s = 0.f, me = 0.f;
        for (int nn = 0; nn < N_; nn++) {
            float e_ = expf(pr[nn] - m);
            s += e_;
            if (nn == n) me = e_;
        }
        pw[r]   = (me / s) * iq;
        invq[r] = iq;
        trow[r] = (t == n);
    }
    __syncthreads();

    // scatter: latent accumulation + latent_target
    for (int idx = tid; idx < 128*128; idx += 256) {
        int r = idx >> 7, e = idx & 127;
        float q = Act[r*ACT_STRIDE + e];
        atomicAdd(&g_lat[(size_t)(b0+r)*E_ + e], pw[r] * q);
        if (trow[r]) out_lt[(size_t)(b0+r)*E_ + e] = q * invq[r];
    }
}

__global__ void enc_finalize(const float* __restrict__ state, float* __restrict__ out)
{
    int warp = (blockIdx.x * blockDim.x + threadIdx.x) >> 5;
    int lane = threadIdx.x & 31;
    if (warp >= B_) return;
    size_t b = warp;

    // log_softmax(cos/TEMP)
    float x0 = (lane      < N_) ? g_cos[b*N_ + lane]      * 10.0f : -INFINITY;
    float x1 = (lane + 32 < N_) ? g_cos[b*N_ + lane + 32] * 10.0f : -INFINITY;
    float m = fmaxf(x0, x1);
    #pragma unroll
    for (int off = 16; off > 0; off >>= 1)
        m = fmaxf(m, __shfl_xor_sync(0xffffffffu, m, off));
    float s = expf(x0 - m) + expf(x1 - m);
    #pragma unroll
    for (int off = 16; off > 0; off >>= 1)
        s += __shfl_xor_sync(0xffffffffu, s, off);
    float lse = m + logf(s);
    float* lp = out + LP_OFF + b*N_;
    if (lane      < N_) lp[lane]      = x0 - lse;
    if (lane + 32 < N_) lp[lane + 32] = x1 - lse;

    // rep_vec = [state, latent_vec]; latent_vec output
    float* rep = out + REP_OFF + b*(S_+E_);
    const float* st = state + b*S_;
    for (int j = lane; j < S_/4; j += 32)
        ((float4*)rep)[j] = ((const float4*)st)[j];
    float* lv = out + LV_OFF + b*E_;
    const float* la = g_lat + b*E_;
    for (int j = lane; j < E_/4; j += 32) {
        float4 v = ((const float4*)la)[j];
        ((float4*)(rep + S_))[j] = v;
        ((float4*)lv)[j] = v;
    }
}

extern "C" void kernel_launch(void* const* d_in, const int* in_sizes, int n_in,
                              void* d_out, int out_size)
{
    const float* state  = (const float*)d_in[0];
    const int*   tid    = (const int*)  d_in[1];
    const float* prior  = (const float*)d_in[2];
    const float* W1     = (const float*)d_in[3];
    const float* b1     = (const float*)d_in[4];
    const float* W2     = (const float*)d_in[5];
    const float* b2     = (const float*)d_in[6];
    const float* W3     = (const float*)d_in[7];
    const float* b3     = (const float*)d_in[8];
    const float* lang   = (const float*)d_in[9];
    float* out = (float*)d_out;

    cudaFuncSetAttribute(enc_main, cudaFuncAttributeMaxDynamicSharedMemorySize, (int)SMEM_BYTES);

    zero_lat_kernel<<<2048, 256>>>();
    enc_main<<<dim3(N_, B_/128), 256, SMEM_BYTES>>>(
        state, tid, prior, W1, b1, W2, b2, W3, b3, lang, out + LT_OFF);
    enc_finalize<<<2048, 256>>>(state, out);
}